// round 2
// baseline (speedup 1.0000x reference)
#include <cuda_runtime.h>
#include <math.h>

#define BD 2
#define HH 64
#define WW 64
#define LL 4096          // H*W
#define DM 96
#define DE 192
#define KD 4
#define NS 16
#define RR 6
#define CD 38            // R + 2N

// ---------------- scratch (device globals, no allocation) ----------------
__device__ float g_xp   [BD*DE*LL];      // conv input, (b, d, h, w)
__device__ float g_z    [BD*LL*DE];      // silu(z), (b*l, d)
__device__ float g_xh   [BD*DE*LL];      // conv out, horizontal order (b,d,h*64+w)
__device__ float g_xv   [BD*DE*LL];      // conv out, vertical order   (b,d,w*64+h)
__device__ float g_delta[BD*KD*DE*LL];   // softplus(dt), (b,k,d,l_local)
__device__ float g_Bs   [BD*KD*LL*NS];   // (b,k,l_local,n)
__device__ float g_Cs   [BD*KD*LL*NS];
__device__ float g_ys   [KD*BD*LL*DE];   // (k,b,l_GLOBAL,d)  <- scatter on store
__device__ float g_yn   [BD*LL*DE];      // after LN*z, (b*l, d)

__device__ __forceinline__ float siluf(float v){ return v * (1.0f/(1.0f+__expf(-v))); }

// ---------------- K1: xz = x @ in_proj_w^T, split into xp / silu(z) -----
// x: (8192,96), w: (384,96). grid (6,128), block 256. BM=BN=64, full-K loop.
__global__ void k1_inproj(const float* __restrict__ x, const float* __restrict__ w)
{
    __shared__ float As[32][65];
    __shared__ float Bs[32][65];
    const int m0 = blockIdx.y*64, n0 = blockIdx.x*64;
    const int tid = threadIdx.x;
    const int ty = tid>>4, tx = tid&15;
    float acc[4][4] = {};

    for (int k0=0;k0<96;k0+=32){
        #pragma unroll
        for (int it=0; it<8; ++it){
            int q = tid + it*256;
            int mm = q>>5, kk = q&31;
            As[kk][mm] = x[(m0+mm)*96 + k0+kk];
            Bs[kk][mm] = w[(n0+mm)*96 + k0+kk];
        }
        __syncthreads();
        #pragma unroll
        for (int kk=0; kk<32; ++kk){
            float a[4], b[4];
            #pragma unroll
            for (int i=0;i<4;i++) a[i] = As[kk][ty*4+i];
            #pragma unroll
            for (int j=0;j<4;j++) b[j] = Bs[kk][tx*4+j];
            #pragma unroll
            for (int i=0;i<4;i++)
                #pragma unroll
                for (int j=0;j<4;j++) acc[i][j] = fmaf(a[i], b[j], acc[i][j]);
        }
        __syncthreads();
    }
    #pragma unroll
    for (int i=0;i<4;i++){
        int row = m0 + ty*4 + i;
        int b = row>>12, l = row&4095;
        #pragma unroll
        for (int j=0;j<4;j++){
            int col = n0 + tx*4 + j;
            float v = acc[i][j];
            if (col < DE) g_xp[(b*DE+col)*LL + l] = v;
            else          g_z[row*DE + (col-DE)] = siluf(v);
        }
    }
}

// ---------------- K2: depthwise 3x3 conv + bias + silu -------------------
// one block per (b,d). writes xh and xv (transposed).
__global__ void k2_conv(const float* __restrict__ cw, const float* __restrict__ cb)
{
    const int bd = blockIdx.x;            // 0..BD*DE-1
    const int d  = bd % DE;
    __shared__ float pl[66][66];
    const float* src = g_xp + bd*LL;
    for (int q=threadIdx.x; q<66*66; q+=256){
        int r=q/66, c=q%66;
        int gh=r-1, gw=c-1;
        float v = 0.f;
        if (gh>=0 && gh<64 && gw>=0 && gw<64) v = src[gh*64+gw];
        pl[r][c] = v;
    }
    float wt[9];
    #pragma unroll
    for (int i=0;i<9;i++) wt[i] = cw[d*9+i];
    float bias = cb[d];
    __syncthreads();
    for (int p=threadIdx.x; p<LL; p+=256){
        int h = p>>6, w = p&63;
        float s = bias;
        #pragma unroll
        for (int dh=0; dh<3; ++dh)
            #pragma unroll
            for (int dw=0; dw<3; ++dw)
                s = fmaf(pl[h+dh][w+dw], wt[dh*3+dw], s);
        float o = siluf(s);
        g_xh[bd*LL + p]          = o;
        g_xv[bd*LL + (w<<6) + h] = o;
    }
}

// ---------------- K3: x_dbl projection + dt projection + softplus --------
// block per (b,k, 32-position tile). grid = BD*KD*(LL/32) = 1024.
__global__ void k3_proj(const float* __restrict__ xpw,
                        const float* __restrict__ dtw,
                        const float* __restrict__ dtb)
{
    const int bx = blockIdx.x;
    const int ltb = bx & 127;
    const int k   = (bx>>7) & 3;
    const int b   = bx>>9;
    const int l0  = ltb*32;
    const bool rev = (k & 1);

    __shared__ float xs_s[DE][33];
    __shared__ float xd_s[CD][33];

    const float* src = (k<2 ? g_xh : g_xv) + (b*DE)*LL;
    for (int q=threadIdx.x; q<DE*32; q+=256){
        int d  = q>>5, lt = q&31;
        int lg = rev ? (LL-1 - (l0+lt)) : (l0+lt);
        xs_s[d][lt] = src[d*LL + lg];
    }
    __syncthreads();

    // phase A: x_dbl[c][lt] = sum_d xs[d][lt] * xpw[k][c][d]
    {
        const int lt = threadIdx.x & 31;
        const int wg = threadIdx.x >> 5;       // 8 warps
        const float* wk = xpw + k*CD*DE;
        for (int c = wg; c < CD; c += 8){
            const float* wr = wk + c*DE;
            float acc = 0.f;
            #pragma unroll 4
            for (int d=0; d<DE; ++d)
                acc = fmaf(xs_s[d][lt], __ldg(&wr[d]), acc);
            xd_s[c][lt] = acc;
        }
    }
    __syncthreads();

    // phase B: delta (softplus), Bs, Cs
    {
        const float* wdt = dtw + k*DE*RR;
        const float* bdt = dtb + k*DE;
        const long base = ((long)(b*KD + k)*DE)*LL;
        for (int q=threadIdx.x; q<DE*32; q+=256){
            int d = q>>5, lt = q&31;
            float acc = __ldg(&bdt[d]);
            #pragma unroll
            for (int r=0;r<RR;r++)
                acc = fmaf(xd_s[r][lt], __ldg(&wdt[d*RR+r]), acc);
            float dl = (acc > 15.f) ? acc : log1pf(__expf(acc));
            g_delta[base + (long)d*LL + (l0+lt)] = dl;
        }
        for (int q=threadIdx.x; q<32*NS; q+=256){
            int lt = q>>4, n = q&15;
            long off = ((long)(b*KD + k)*LL + (l0+lt))*NS + n;
            g_Bs[off] = xd_s[RR     + n][lt];
            g_Cs[off] = xd_s[RR+NS + n][lt];
        }
    }
}

// ---------------- K4: selective scan ------------------------------------
// grid = BD*KD*(DE/16) = 96 blocks, 256 threads: 16 lanes (d) x 16 states (n).
// Writer thread scatters y directly to the GLOBAL output position
// (un-reversal + H/W transpose folded in) so the combine kernel is coalesced.
__global__ void k4_scan(const float* __restrict__ A_logs, const float* __restrict__ Ds)
{
    const int blk = blockIdx.x;
    const int dg = blk % 12;
    const int k  = (blk/12) % 4;
    const int b  = blk / 48;
    const int lane = threadIdx.x >> 4;
    const int n    = threadIdx.x & 15;
    const int d    = dg*16 + lane;
    const int row  = k*DE + d;

    const float an = -__expf(A_logs[row*NS + n]);
    const float ds = Ds[row];
    const bool rev = (k & 1);
    const bool vert = (k >= 2);

    const float* dptr = g_delta + ((long)(b*KD + k)*DE + d)*LL;
    const float* usrc = (vert ? g_xv : g_xh) + ((long)(b*DE + d))*LL;
    const float* bptr = g_Bs + ((long)(b*KD + k)*LL)*NS + n;
    const float* cptr = g_Cs + ((long)(b*KD + k)*LL)*NS + n;
    float* ybase = g_ys + ((long)(k*BD + b)*LL)*DE + d;

    const int u0  = rev ? (LL-1) : 0;
    const int ust = rev ? -1 : 1;

    float h = 0.f;
    #pragma unroll 4
    for (int t=0; t<LL; ++t){
        float dt = dptr[t];
        float u  = usrc[u0 + ust*t];
        float bn = bptr[(long)t*NS];
        float cn = cptr[(long)t*NS];
        float dA = __expf(dt * an);
        h = fmaf(dA, h, dt * u * bn);
        float p = h * cn;
        p += __shfl_xor_sync(0xffffffffu, p, 1, 16);
        p += __shfl_xor_sync(0xffffffffu, p, 2, 16);
        p += __shfl_xor_sync(0xffffffffu, p, 4, 16);
        p += __shfl_xor_sync(0xffffffffu, p, 8, 16);
        if (n == 0){
            int lv = u0 + ust*t;                      // direction-local forward index
            int lg = vert ? (((lv&63)<<6) | (lv>>6))  // transpose back to h*64+w
                          : lv;
            ybase[(long)lg*DE] = p + u * ds;
        }
    }
}

// ---------------- K5: combine 4 dirs + LayerNorm + z-gate ----------------
__global__ void k5_ln(const float* __restrict__ scale, const float* __restrict__ bias)
{
    const int pos = blockIdx.x;              // b*4096 + l
    const int b = pos >> 12;
    const int l = pos & 4095;
    const int d = threadIdx.x;               // 192 threads

    float v = 0.f;
    #pragma unroll
    for (int k=0; k<KD; ++k)
        v += g_ys[((long)(k*BD + b)*LL + l)*DE + d];

    float s = v, sq = v*v;
    #pragma unroll
    for (int off=16; off>0; off>>=1){
        s  += __shfl_xor_sync(0xffffffffu, s,  off);
        sq += __shfl_xor_sync(0xffffffffu, sq, off);
    }
    __shared__ float ss[6], sqq[6];
    if ((threadIdx.x & 31) == 0){ ss[threadIdx.x>>5] = s; sqq[threadIdx.x>>5] = sq; }
    __syncthreads();
    float tot=0.f, totq=0.f;
    #pragma unroll
    for (int w=0; w<6; ++w){ tot += ss[w]; totq += sqq[w]; }
    float mu  = tot * (1.0f/DE);
    float var = totq * (1.0f/DE) - mu*mu;
    float rstd = rsqrtf(var + 1e-5f);
    float yn = (v - mu)*rstd*scale[d] + bias[d];
    g_yn[(long)pos*DE + d] = yn * g_z[(long)pos*DE + d];
}

// ---------------- K6: out = yn @ out_proj_w^T ---------------------------
// yn: (8192,192), w: (96,192). BM=64, BN=96, BK=32. grid 128, block 256.
__global__ void k6_outproj(const float* __restrict__ w, float* __restrict__ out)
{
    __shared__ float As[32][65];
    __shared__ float Bs[32][97];
    const int m0 = blockIdx.x*64;
    const int tid = threadIdx.x;
    const int ty = tid>>4, tx = tid&15;       // ty: 16 row groups of 4, tx: 16 col groups of 6
    float acc[4][6] = {};

    for (int k0=0;k0<DE;k0+=32){
        #pragma unroll
        for (int it=0; it<8; ++it){
            int q = tid + it*256;
            int mm = q>>5, kk = q&31;
            As[kk][mm] = g_yn[(long)(m0+mm)*DE + k0+kk];
        }
        #pragma unroll
        for (int it=0; it<12; ++it){
            int q = tid + it*256;
            int nn = q>>5, kk = q&31;
            Bs[kk][nn] = w[nn*DE + k0+kk];
        }
        __syncthreads();
        #pragma unroll
        for (int kk=0; kk<32; ++kk){
            float a[4], bb[6];
            #pragma unroll
            for (int i=0;i<4;i++) a[i] = As[kk][ty*4+i];
            #pragma unroll
            for (int j=0;j<6;j++) bb[j] = Bs[kk][tx*6+j];
            #pragma unroll
            for (int i=0;i<4;i++)
                #pragma unroll
                for (int j=0;j<6;j++) acc[i][j] = fmaf(a[i], bb[j], acc[i][j]);
        }
        __syncthreads();
    }
    #pragma unroll
    for (int i=0;i<4;i++){
        int rowi = m0 + ty*4 + i;
        #pragma unroll
        for (int j=0;j<6;j++)
            out[(long)rowi*DM + tx*6 + j] = acc[i][j];
    }
}

// ---------------- launch -------------------------------------------------
extern "C" void kernel_launch(void* const* d_in, const int* in_sizes, int n_in,
                              void* d_out, int out_size)
{
    const float* x    = (const float*)d_in[0];
    const float* ipw  = (const float*)d_in[1];
    const float* cw   = (const float*)d_in[2];
    const float* cb   = (const float*)d_in[3];
    const float* xpw  = (const float*)d_in[4];
    const float* dtw  = (const float*)d_in[5];
    const float* dtb  = (const float*)d_in[6];
    const float* alog = (const float*)d_in[7];
    const float* dsv  = (const float*)d_in[8];
    const float* lnsc = (const float*)d_in[9];
    const float* lnbi = (const float*)d_in[10];
    const float* opw  = (const float*)d_in[11];
    float* out = (float*)d_out;

    k1_inproj<<<dim3(6,128), 256>>>(x, ipw);
    k2_conv  <<<BD*DE, 256>>>(cw, cb);
    k3_proj  <<<BD*KD*(LL/32), 256>>>(xpw, dtw, dtb);
    k4_scan  <<<BD*KD*(DE/16), 256>>>(alog, dsv);
    k5_ln    <<<BD*LL, DE>>>(lnsc, lnbi);
    k6_outproj<<<128, 256>>>(opw, out);
}

// round 4
// speedup vs baseline: 4.0450x; 4.0450x over previous
#include <cuda_runtime.h>
#include <math.h>

#define BD 2
#define HH 64
#define WW 64
#define LL 4096          // H*W
#define DM 96
#define DE 192
#define KD 4
#define NS 16
#define RR 6
#define CD 38            // R + 2N
#define CH 64            // number of chunks
#define CT 64            // steps per chunk

// ---------------- scratch (device globals, no allocation) ----------------
__device__ float g_xp   [BD*DE*LL];      // conv input, (b, d, h, w)
__device__ float g_z    [BD*LL*DE];      // silu(z), (b*l, d)
__device__ float g_xh   [BD*DE*LL];      // conv out, horizontal order (b,d,h*64+w)
__device__ float g_xv   [BD*DE*LL];      // conv out, vertical order   (b,d,w*64+h)
__device__ float g_delta[BD*KD*DE*LL];   // softplus(dt), (b,k,d,l_local)
__device__ float g_Bs   [BD*KD*LL*NS];   // (b,k,l_local,n)
__device__ float g_Cs   [BD*KD*LL*NS];
__device__ float g_S    [BD*KD*DE*CH*NS];  // chunk-local final state
__device__ float g_P    [BD*KD*DE*CH*NS];  // chunk decay product
__device__ float g_H0   [BD*KD*DE*CH*NS];  // chunk true initial state
__device__ float g_ys   [KD*BD*LL*DE];   // (k,b,l_GLOBAL,d)  <- scatter on store
__device__ float g_yn   [BD*LL*DE];      // after LN*z, (b*l, d)

__device__ __forceinline__ float siluf(float v){ return v * (1.0f/(1.0f+__expf(-v))); }

// ---------------- K1: xz = x @ in_proj_w^T, split into xp / silu(z) -----
__global__ void k1_inproj(const float* __restrict__ x, const float* __restrict__ w)
{
    __shared__ float As[32][65];
    __shared__ float Bs[32][65];
    const int m0 = blockIdx.y*64, n0 = blockIdx.x*64;
    const int tid = threadIdx.x;
    const int ty = tid>>4, tx = tid&15;
    float acc[4][4] = {};

    for (int k0=0;k0<96;k0+=32){
        #pragma unroll
        for (int it=0; it<8; ++it){
            int q = tid + it*256;
            int mm = q>>5, kk = q&31;
            As[kk][mm] = x[(m0+mm)*96 + k0+kk];
            Bs[kk][mm] = w[(n0+mm)*96 + k0+kk];
        }
        __syncthreads();
        #pragma unroll
        for (int kk=0; kk<32; ++kk){
            float a[4], b[4];
            #pragma unroll
            for (int i=0;i<4;i++) a[i] = As[kk][ty*4+i];
            #pragma unroll
            for (int j=0;j<4;j++) b[j] = Bs[kk][tx*4+j];
            #pragma unroll
            for (int i=0;i<4;i++)
                #pragma unroll
                for (int j=0;j<4;j++) acc[i][j] = fmaf(a[i], b[j], acc[i][j]);
        }
        __syncthreads();
    }
    #pragma unroll
    for (int i=0;i<4;i++){
        int row = m0 + ty*4 + i;
        int b = row>>12, l = row&4095;
        #pragma unroll
        for (int j=0;j<4;j++){
            int col = n0 + tx*4 + j;
            float v = acc[i][j];
            if (col < DE) g_xp[(b*DE+col)*LL + l] = v;
            else          g_z[row*DE + (col-DE)] = siluf(v);
        }
    }
}

// ---------------- K2: depthwise 3x3 conv + bias + silu -------------------
__global__ void k2_conv(const float* __restrict__ cw, const float* __restrict__ cb)
{
    const int bd = blockIdx.x;
    const int d  = bd % DE;
    __shared__ float pl[66][66];
    const float* src = g_xp + bd*LL;
    for (int q=threadIdx.x; q<66*66; q+=256){
        int r=q/66, c=q%66;
        int gh=r-1, gw=c-1;
        float v = 0.f;
        if (gh>=0 && gh<64 && gw>=0 && gw<64) v = src[gh*64+gw];
        pl[r][c] = v;
    }
    float wt[9];
    #pragma unroll
    for (int i=0;i<9;i++) wt[i] = cw[d*9+i];
    float bias = cb[d];
    __syncthreads();
    for (int p=threadIdx.x; p<LL; p+=256){
        int h = p>>6, w = p&63;
        float s = bias;
        #pragma unroll
        for (int dh=0; dh<3; ++dh)
            #pragma unroll
            for (int dw=0; dw<3; ++dw)
                s = fmaf(pl[h+dh][w+dw], wt[dh*3+dw], s);
        float o = siluf(s);
        g_xh[bd*LL + p]          = o;
        g_xv[bd*LL + (w<<6) + h] = o;
    }
}

// ---------------- K3: x_dbl projection + dt projection + softplus --------
__global__ void k3_proj(const float* __restrict__ xpw,
                        const float* __restrict__ dtw,
                        const float* __restrict__ dtb)
{
    const int bx = blockIdx.x;
    const int ltb = bx & 127;
    const int k   = (bx>>7) & 3;
    const int b   = bx>>9;
    const int l0  = ltb*32;
    const bool rev = (k & 1);

    __shared__ float xs_s[DE][33];
    __shared__ float xd_s[CD][33];

    const float* src = (k<2 ? g_xh : g_xv) + (b*DE)*LL;
    for (int q=threadIdx.x; q<DE*32; q+=256){
        int d  = q>>5, lt = q&31;
        int lg = rev ? (LL-1 - (l0+lt)) : (l0+lt);
        xs_s[d][lt] = src[d*LL + lg];
    }
    __syncthreads();

    {
        const int lt = threadIdx.x & 31;
        const int wg = threadIdx.x >> 5;
        const float* wk = xpw + k*CD*DE;
        for (int c = wg; c < CD; c += 8){
            const float* wr = wk + c*DE;
            float acc = 0.f;
            #pragma unroll 4
            for (int d=0; d<DE; ++d)
                acc = fmaf(xs_s[d][lt], __ldg(&wr[d]), acc);
            xd_s[c][lt] = acc;
        }
    }
    __syncthreads();

    {
        const float* wdt = dtw + k*DE*RR;
        const float* bdt = dtb + k*DE;
        const long base = ((long)(b*KD + k)*DE)*LL;
        for (int q=threadIdx.x; q<DE*32; q+=256){
            int d = q>>5, lt = q&31;
            float acc = __ldg(&bdt[d]);
            #pragma unroll
            for (int r=0;r<RR;r++)
                acc = fmaf(xd_s[r][lt], __ldg(&wdt[d*RR+r]), acc);
            float dl = (acc > 15.f) ? acc : log1pf(__expf(acc));
            g_delta[base + (long)d*LL + (l0+lt)] = dl;
        }
        for (int q=threadIdx.x; q<32*NS; q+=256){
            int lt = q>>4, n = q&15;
            long off = ((long)(b*KD + k)*LL + (l0+lt))*NS + n;
            g_Bs[off] = xd_s[RR     + n][lt];
            g_Cs[off] = xd_s[RR+NS + n][lt];
        }
    }
}

// ---------------- K4a: per-chunk local scan (h0 = 0) ---------------------
// grid = BD*KD*12*CH = 6144 blocks, 256 threads: 16 d-lanes x 16 states.
__global__ void k4a_chunk(const float* __restrict__ A_logs)
{
    const int blk = blockIdx.x;
    const int c  = blk & (CH-1);
    const int dg = (blk>>6) % 12;
    const int bk = blk / (CH*12);      // b*KD + k
    const int k  = bk & 3;
    const int b  = bk >> 2;
    const int tid = threadIdx.x;
    const int dl = tid >> 4;
    const int n  = tid & 15;
    const int d  = dg*16 + dl;
    const bool rev  = (k & 1);
    const bool vert = (k >= 2);

    __shared__ float sdt[16][CT];
    __shared__ float su [16][CT];
    __shared__ float sB [CT][NS];

    const int tloc0 = c*CT;
    {
        const float* dbase = g_delta + ((long)bk*DE + dg*16)*LL + tloc0;
        const float* ubase = (vert ? g_xv : g_xh) + ((long)(b*DE) + dg*16)*LL;
        for (int q=tid; q<16*CT; q+=256){
            int dd = q>>6, t = q&63;
            sdt[dd][t] = dbase[dd*LL + t];
            int lv = rev ? (LL-1 - (tloc0+t)) : (tloc0+t);
            su[dd][t] = ubase[dd*LL + lv];
        }
        const float* bbase = g_Bs + ((long)bk*LL + tloc0)*NS;
        for (int q=tid; q<CT*NS; q+=256)
            sB[q>>4][q&15] = bbase[q];
    }
    const float an = -__expf(A_logs[(k*DE+d)*NS + n]);
    __syncthreads();

    float h = 0.f, P = 1.f;
    #pragma unroll 8
    for (int t=0; t<CT; ++t){
        float dt = sdt[dl][t];
        float dA = __expf(dt*an);
        h = fmaf(dA, h, dt * su[dl][t] * sB[t][n]);
        P *= dA;
    }
    long so = ((long)(bk*DE + d)*CH + c)*NS + n;
    g_S[so] = h;
    g_P[so] = P;
}

// ---------------- K4m: compose chunk states sequentially -----------------
// 24576 lanes, each walks 64 chunks: H0[c] = h; h = P[c]*h + S[c].
__global__ void k4m_combine()
{
    const int idx = blockIdx.x*256 + threadIdx.x;   // (bk,d,n)
    const int n  = idx & 15;
    const int d  = (idx >> 4) % DE;
    const int bk = idx / (DE*NS);
    const long base = ((long)(bk*DE + d)*CH)*NS + n;
    float h = 0.f;
    #pragma unroll 4
    for (int c=0; c<CH; ++c){
        long o = base + (long)c*NS;
        float P = g_P[o];
        float S = g_S[o];
        g_H0[o] = h;
        h = fmaf(P, h, S);
    }
}

// ---------------- K4c: per-chunk scan with true h0, emit y ---------------
__global__ void k4c_emit(const float* __restrict__ A_logs, const float* __restrict__ Ds)
{
    const int blk = blockIdx.x;
    const int c  = blk & (CH-1);
    const int dg = (blk>>6) % 12;
    const int bk = blk / (CH*12);
    const int k  = bk & 3;
    const int b  = bk >> 2;
    const int tid = threadIdx.x;
    const int dl = tid >> 4;
    const int n  = tid & 15;
    const int d  = dg*16 + dl;
    const bool rev  = (k & 1);
    const bool vert = (k >= 2);

    __shared__ float sdt[16][CT];
    __shared__ float su [16][CT];
    __shared__ float sB [CT][NS];
    __shared__ float sC [CT][NS];
    __shared__ float sy [CT][17];

    const int tloc0 = c*CT;
    {
        const float* dbase = g_delta + ((long)bk*DE + dg*16)*LL + tloc0;
        const float* ubase = (vert ? g_xv : g_xh) + ((long)(b*DE) + dg*16)*LL;
        for (int q=tid; q<16*CT; q+=256){
            int dd = q>>6, t = q&63;
            sdt[dd][t] = dbase[dd*LL + t];
            int lv = rev ? (LL-1 - (tloc0+t)) : (tloc0+t);
            su[dd][t] = ubase[dd*LL + lv];
        }
        const float* bbase = g_Bs + ((long)bk*LL + tloc0)*NS;
        const float* cbase = g_Cs + ((long)bk*LL + tloc0)*NS;
        for (int q=tid; q<CT*NS; q+=256){
            sB[q>>4][q&15] = bbase[q];
            sC[q>>4][q&15] = cbase[q];
        }
    }
    const float an = -__expf(A_logs[(k*DE+d)*NS + n]);
    const float ds = Ds[k*DE + d];
    float h = g_H0[((long)(bk*DE + d)*CH + c)*NS + n];
    __syncthreads();

    #pragma unroll 4
    for (int t=0; t<CT; ++t){
        float dt = sdt[dl][t];
        float dA = __expf(dt*an);
        h = fmaf(dA, h, dt * su[dl][t] * sB[t][n]);
        float p = h * sC[t][n];
        p += __shfl_xor_sync(0xffffffffu, p, 1, 16);
        p += __shfl_xor_sync(0xffffffffu, p, 2, 16);
        p += __shfl_xor_sync(0xffffffffu, p, 4, 16);
        p += __shfl_xor_sync(0xffffffffu, p, 8, 16);
        if (n == 0) sy[t][dl] = p + su[dl][t]*ds;
    }
    __syncthreads();

    // coalesced scattered-tile store: 16 d columns x 64 positions
    float* ybase = g_ys + ((long)(k*BD + b)*LL)*DE + dg*16;
    for (int q=tid; q<CT*16; q+=256){
        int t = q>>4, j = q&15;
        int tloc = tloc0 + t;
        int lv = rev ? (LL-1 - tloc) : tloc;
        int lg = vert ? (((lv&63)<<6) | (lv>>6)) : lv;
        ybase[(long)lg*DE + j] = sy[t][j];
    }
}

// ---------------- K5: combine 4 dirs + LayerNorm + z-gate ----------------
__global__ void k5_ln(const float* __restrict__ scale, const float* __restrict__ bias)
{
    const int pos = blockIdx.x;
    const int b = pos >> 12;
    const int l = pos & 4095;
    const int d = threadIdx.x;

    float v = 0.f;
    #pragma unroll
    for (int k=0; k<KD; ++k)
        v += g_ys[((long)(k*BD + b)*LL + l)*DE + d];

    float s = v, sq = v*v;
    #pragma unroll
    for (int off=16; off>0; off>>=1){
        s  += __shfl_xor_sync(0xffffffffu, s,  off);
        sq += __shfl_xor_sync(0xffffffffu, sq, off);
    }
    __shared__ float ss[6], sqq[6];
    if ((threadIdx.x & 31) == 0){ ss[threadIdx.x>>5] = s; sqq[threadIdx.x>>5] = sq; }
    __syncthreads();
    float tot=0.f, totq=0.f;
    #pragma unroll
    for (int w=0; w<6; ++w){ tot += ss[w]; totq += sqq[w]; }
    float mu  = tot * (1.0f/DE);
    float var = totq * (1.0f/DE) - mu*mu;
    float rstd = rsqrtf(var + 1e-5f);
    float yn = (v - mu)*rstd*scale[d] + bias[d];
    g_yn[(long)pos*DE + d] = yn * g_z[(long)pos*DE + d];
}

// ---------------- K6: out = yn @ out_proj_w^T ---------------------------
__global__ void k6_outproj(const float* __restrict__ w, float* __restrict__ out)
{
    __shared__ float As[32][65];
    __shared__ float Bs[32][97];
    const int m0 = blockIdx.x*64;
    const int tid = threadIdx.x;
    const int ty = tid>>4, tx = tid&15;
    float acc[4][6] = {};

    for (int k0=0;k0<DE;k0+=32){
        #pragma unroll
        for (int it=0; it<8; ++it){
            int q = tid + it*256;
            int mm = q>>5, kk = q&31;
            As[kk][mm] = g_yn[(long)(m0+mm)*DE + k0+kk];
        }
        #pragma unroll
        for (int it=0; it<12; ++it){
            int q = tid + it*256;
            int nn = q>>5, kk = q&31;
            Bs[kk][nn] = w[nn*DE + k0+kk];
        }
        __syncthreads();
        #pragma unroll
        for (int kk=0; kk<32; ++kk){
            float a[4], bb[6];
            #pragma unroll
            for (int i=0;i<4;i++) a[i] = As[kk][ty*4+i];
            #pragma unroll
            for (int j=0;j<6;j++) bb[j] = Bs[kk][tx*6+j];
            #pragma unroll
            for (int i=0;i<4;i++)
                #pragma unroll
                for (int j=0;j<6;j++) acc[i][j] = fmaf(a[i], bb[j], acc[i][j]);
        }
        __syncthreads();
    }
    #pragma unroll
    for (int i=0;i<4;i++){
        int rowi = m0 + ty*4 + i;
        #pragma unroll
        for (int j=0;j<6;j++)
            out[(long)rowi*DM + tx*6 + j] = acc[i][j];
    }
}

// ---------------- launch -------------------------------------------------
extern "C" void kernel_launch(void* const* d_in, const int* in_sizes, int n_in,
                              void* d_out, int out_size)
{
    const float* x    = (const float*)d_in[0];
    const float* ipw  = (const float*)d_in[1];
    const float* cw   = (const float*)d_in[2];
    const float* cb   = (const float*)d_in[3];
    const float* xpw  = (const float*)d_in[4];
    const float* dtw  = (const float*)d_in[5];
    const float* dtb  = (const float*)d_in[6];
    const float* alog = (const float*)d_in[7];
    const float* dsv  = (const float*)d_in[8];
    const float* lnsc = (const float*)d_in[9];
    const float* lnbi = (const float*)d_in[10];
    const float* opw  = (const float*)d_in[11];
    float* out = (float*)d_out;

    k1_inproj<<<dim3(6,128), 256>>>(x, ipw);
    k2_conv  <<<BD*DE, 256>>>(cw, cb);
    k3_proj  <<<BD*KD*(LL/32), 256>>>(xpw, dtw, dtb);
    k4a_chunk<<<BD*KD*12*CH, 256>>>(alog);
    k4m_combine<<<BD*KD*DE*NS/256, 256>>>();
    k4c_emit <<<BD*KD*12*CH, 256>>>(alog, dsv);
    k5_ln    <<<BD*LL, DE>>>(lnsc, lnbi);
    k6_outproj<<<128, 256>>>(opw, out);
}

// round 5
// speedup vs baseline: 6.2679x; 1.5495x over previous
#include <cuda_runtime.h>
#include <math.h>

#define BD 2
#define HH 64
#define WW 64
#define LL 4096          // H*W
#define DM 96
#define DE 192
#define KD 4
#define NS 16
#define RR 6
#define CD 38            // R + 2N
#define CH 64            // number of chunks
#define CT 64            // steps per chunk

// ---------------- scratch (device globals, no allocation) ----------------
__device__ float g_xp   [BD*DE*LL];
__device__ float g_z    [BD*LL*DE];
__device__ float g_xh   [BD*DE*LL];
__device__ float g_xv   [BD*DE*LL];
__device__ float g_delta[BD*KD*DE*LL];
__device__ float g_Bs   [BD*KD*LL*NS];
__device__ float g_Cs   [BD*KD*LL*NS];
__device__ float g_S    [BD*KD*DE*CH*NS];
__device__ float g_P    [BD*KD*DE*CH*NS];
__device__ float g_H0   [BD*KD*DE*CH*NS];
__device__ float g_ys   [KD*BD*LL*DE];
__device__ float g_yn   [BD*LL*DE];

__device__ __forceinline__ float siluf(float v){ return v * (1.0f/(1.0f+__expf(-v))); }
__device__ __forceinline__ float ex2f(float x){ float r; asm("ex2.approx.ftz.f32 %0, %1;" : "=f"(r) : "f"(x)); return r; }
#define LOG2E 1.44269504f

// ---------------- K1: xz = x @ in_proj_w^T, split into xp / silu(z) -----
__global__ void k1_inproj(const float* __restrict__ x, const float* __restrict__ w)
{
    __shared__ float As[32][65];
    __shared__ float Bs[32][65];
    const int m0 = blockIdx.y*64, n0 = blockIdx.x*64;
    const int tid = threadIdx.x;
    const int ty = tid>>4, tx = tid&15;
    float acc[4][4] = {};

    for (int k0=0;k0<96;k0+=32){
        #pragma unroll
        for (int it=0; it<8; ++it){
            int q = tid + it*256;
            int mm = q>>5, kk = q&31;
            As[kk][mm] = x[(m0+mm)*96 + k0+kk];
            Bs[kk][mm] = w[(n0+mm)*96 + k0+kk];
        }
        __syncthreads();
        #pragma unroll
        for (int kk=0; kk<32; ++kk){
            float a[4], b[4];
            #pragma unroll
            for (int i=0;i<4;i++) a[i] = As[kk][ty*4+i];
            #pragma unroll
            for (int j=0;j<4;j++) b[j] = Bs[kk][tx*4+j];
            #pragma unroll
            for (int i=0;i<4;i++)
                #pragma unroll
                for (int j=0;j<4;j++) acc[i][j] = fmaf(a[i], b[j], acc[i][j]);
        }
        __syncthreads();
    }
    #pragma unroll
    for (int i=0;i<4;i++){
        int row = m0 + ty*4 + i;
        int b = row>>12, l = row&4095;
        #pragma unroll
        for (int j=0;j<4;j++){
            int col = n0 + tx*4 + j;
            float v = acc[i][j];
            if (col < DE) g_xp[(b*DE+col)*LL + l] = v;
            else          g_z[row*DE + (col-DE)] = siluf(v);
        }
    }
}

// ---------------- K2: depthwise 3x3 conv + bias + silu -------------------
__global__ void k2_conv(const float* __restrict__ cw, const float* __restrict__ cb)
{
    const int bd = blockIdx.x;
    const int d  = bd % DE;
    __shared__ float pl[66][66];
    const float* src = g_xp + bd*LL;
    for (int q=threadIdx.x; q<66*66; q+=256){
        int r=q/66, c=q%66;
        int gh=r-1, gw=c-1;
        float v = 0.f;
        if (gh>=0 && gh<64 && gw>=0 && gw<64) v = src[gh*64+gw];
        pl[r][c] = v;
    }
    float wt[9];
    #pragma unroll
    for (int i=0;i<9;i++) wt[i] = cw[d*9+i];
    float bias = cb[d];
    __syncthreads();
    for (int p=threadIdx.x; p<LL; p+=256){
        int h = p>>6, w = p&63;
        float s = bias;
        #pragma unroll
        for (int dh=0; dh<3; ++dh)
            #pragma unroll
            for (int dw=0; dw<3; ++dw)
                s = fmaf(pl[h+dh][w+dw], wt[dh*3+dw], s);
        float o = siluf(s);
        g_xh[bd*LL + p]          = o;
        g_xv[bd*LL + (w<<6) + h] = o;
    }
}

// ---------------- K3: x_dbl projection + dt projection + softplus --------
__global__ void k3_proj(const float* __restrict__ xpw,
                        const float* __restrict__ dtw,
                        const float* __restrict__ dtb)
{
    const int bx = blockIdx.x;
    const int ltb = bx & 127;
    const int k   = (bx>>7) & 3;
    const int b   = bx>>9;
    const int l0  = ltb*32;
    const bool rev = (k & 1);

    __shared__ float xs_s[DE][33];
    __shared__ float xd_s[CD][33];

    const float* src = (k<2 ? g_xh : g_xv) + (b*DE)*LL;
    for (int q=threadIdx.x; q<DE*32; q+=256){
        int d  = q>>5, lt = q&31;
        int lg = rev ? (LL-1 - (l0+lt)) : (l0+lt);
        xs_s[d][lt] = src[d*LL + lg];
    }
    __syncthreads();

    // phase A: register-blocked over 5 c-rows per warp
    {
        const int lt = threadIdx.x & 31;
        const int wg = threadIdx.x >> 5;
        const float* wk = xpw + k*CD*DE;
        float acc[5] = {0.f,0.f,0.f,0.f,0.f};
        #pragma unroll 2
        for (int d=0; d<DE; ++d){
            float xv = xs_s[d][lt];
            #pragma unroll
            for (int j=0;j<5;j++){
                int c = wg + 8*j;
                if (c < CD) acc[j] = fmaf(xv, __ldg(&wk[c*DE+d]), acc[j]);
            }
        }
        #pragma unroll
        for (int j=0;j<5;j++){
            int c = wg + 8*j;
            if (c < CD) xd_s[c][lt] = acc[j];
        }
    }
    __syncthreads();

    {
        const float* wdt = dtw + k*DE*RR;
        const float* bdt = dtb + k*DE;
        const long base = ((long)(b*KD + k)*DE)*LL;
        for (int q=threadIdx.x; q<DE*32; q+=256){
            int d = q>>5, lt = q&31;
            float acc = __ldg(&bdt[d]);
            #pragma unroll
            for (int r=0;r<RR;r++)
                acc = fmaf(xd_s[r][lt], __ldg(&wdt[d*RR+r]), acc);
            float dl = (acc > 15.f) ? acc : log1pf(__expf(acc));
            g_delta[base + (long)d*LL + (l0+lt)] = dl;
        }
        for (int q=threadIdx.x; q<32*NS; q+=256){
            int lt = q>>4, n = q&15;
            long off = ((long)(b*KD + k)*LL + (l0+lt))*NS + n;
            g_Bs[off] = xd_s[RR     + n][lt];
            g_Cs[off] = xd_s[RR+NS + n][lt];
        }
    }
}

// ---------------- K4a: per-chunk local scan (h0 = 0) ---------------------
// grid = BD*KD*3*CH = 1536 blocks. 256 threads = 64 d-lanes x 4 n-quads.
__global__ void k4a_chunk(const float* __restrict__ A_logs)
{
    const int blk = blockIdx.x;
    const int c  = blk & (CH-1);
    const int dg = (blk>>6) % 3;
    const int bk = blk / (CH*3);       // b*KD + k
    const int k  = bk & 3;
    const int b  = bk >> 2;
    const int tid = threadIdx.x;
    const int dl = tid >> 2;           // 0..63
    const int nq = tid & 3;            // n-quad
    const int d  = dg*64 + dl;
    const bool rev  = (k & 1);
    const bool vert = (k >= 2);

    __shared__ float  sdt[64][CT+1];
    __shared__ float  su [64][CT+1];
    __shared__ float4 sB4[CT][4];

    const int tloc0 = c*CT;
    {
        const float* dbase = g_delta + ((long)bk*DE + dg*64)*LL + tloc0;
        const float* ubase = (vert ? g_xv : g_xh) + ((long)(b*DE) + dg*64)*LL;
        #pragma unroll
        for (int q=tid; q<64*CT; q+=256){
            int dd = q>>6, t = q&63;
            sdt[dd][t] = dbase[dd*LL + t];
            int lv = rev ? (LL-1 - (tloc0+t)) : (tloc0+t);
            su[dd][t] = ubase[dd*LL + lv];
        }
        const float4* bb = (const float4*)(g_Bs + ((long)bk*LL + tloc0)*NS);
        sB4[tid>>2][tid&3] = bb[tid];
    }
    const float4 al = *(const float4*)(A_logs + ((long)(k*DE+d))*NS + nq*4);
    const float an0 = -__expf(al.x)*LOG2E;
    const float an1 = -__expf(al.y)*LOG2E;
    const float an2 = -__expf(al.z)*LOG2E;
    const float an3 = -__expf(al.w)*LOG2E;
    __syncthreads();

    float h0=0.f,h1=0.f,h2=0.f,h3=0.f,dts=0.f;
    #pragma unroll 4
    for (int t=0; t<CT; ++t){
        float dt = sdt[dl][t];
        float u  = su[dl][t];
        float4 bv = sB4[t][nq];
        float dtu = dt*u;
        dts += dt;
        h0 = fmaf(ex2f(dt*an0), h0, dtu*bv.x);
        h1 = fmaf(ex2f(dt*an1), h1, dtu*bv.y);
        h2 = fmaf(ex2f(dt*an2), h2, dtu*bv.z);
        h3 = fmaf(ex2f(dt*an3), h3, dtu*bv.w);
    }
    long so = (((long)bk*DE + d)*CH + c)*NS + nq*4;
    *(float4*)(g_S + so) = make_float4(h0,h1,h2,h3);
    *(float4*)(g_P + so) = make_float4(ex2f(an0*dts), ex2f(an1*dts),
                                       ex2f(an2*dts), ex2f(an3*dts));
}

// ---------------- K4m: compose chunk states sequentially -----------------
__global__ void k4m_combine()
{
    const int idx = blockIdx.x*256 + threadIdx.x;   // (bk,d,n)
    const int n  = idx & 15;
    const int d  = (idx >> 4) % DE;
    const int bk = idx / (DE*NS);
    const long base = ((long)(bk*DE + d)*CH)*NS + n;
    float h = 0.f;
    #pragma unroll 4
    for (int c=0; c<CH; ++c){
        long o = base + (long)c*NS;
        float P = g_P[o];
        float S = g_S[o];
        g_H0[o] = h;
        h = fmaf(P, h, S);
    }
}

// ---------------- K4c: per-chunk scan with true h0, emit y ---------------
__global__ void k4c_emit(const float* __restrict__ A_logs, const float* __restrict__ Ds)
{
    const int blk = blockIdx.x;
    const int c  = blk & (CH-1);
    const int dg = (blk>>6) % 3;
    const int bk = blk / (CH*3);
    const int k  = bk & 3;
    const int b  = bk >> 2;
    const int tid = threadIdx.x;
    const int dl = tid >> 2;
    const int nq = tid & 3;
    const int d  = dg*64 + dl;
    const bool rev  = (k & 1);
    const bool vert = (k >= 2);

    __shared__ float  sdt[64][CT+1];
    __shared__ float  su [64][CT+1];   // reused for y after consumption
    __shared__ float4 sB4[CT][4];
    __shared__ float4 sC4[CT][4];

    const int tloc0 = c*CT;
    {
        const float* dbase = g_delta + ((long)bk*DE + dg*64)*LL + tloc0;
        const float* ubase = (vert ? g_xv : g_xh) + ((long)(b*DE) + dg*64)*LL;
        #pragma unroll
        for (int q=tid; q<64*CT; q+=256){
            int dd = q>>6, t = q&63;
            sdt[dd][t] = dbase[dd*LL + t];
            int lv = rev ? (LL-1 - (tloc0+t)) : (tloc0+t);
            su[dd][t] = ubase[dd*LL + lv];
        }
        const float4* bb = (const float4*)(g_Bs + ((long)bk*LL + tloc0)*NS);
        const float4* cc = (const float4*)(g_Cs + ((long)bk*LL + tloc0)*NS);
        sB4[tid>>2][tid&3] = bb[tid];
        sC4[tid>>2][tid&3] = cc[tid];
    }
    const float4 al = *(const float4*)(A_logs + ((long)(k*DE+d))*NS + nq*4);
    const float an0 = -__expf(al.x)*LOG2E;
    const float an1 = -__expf(al.y)*LOG2E;
    const float an2 = -__expf(al.z)*LOG2E;
    const float an3 = -__expf(al.w)*LOG2E;
    const float ds  = Ds[k*DE + d];
    const float4 h4 = *(const float4*)(g_H0 + (((long)bk*DE + d)*CH + c)*NS + nq*4);
    float h0=h4.x, h1=h4.y, h2=h4.z, h3=h4.w;
    __syncthreads();

    #pragma unroll 2
    for (int t=0; t<CT; ++t){
        float dt = sdt[dl][t];
        float u  = su[dl][t];
        float4 bv = sB4[t][nq];
        float4 cv = sC4[t][nq];
        float dtu = dt*u;
        h0 = fmaf(ex2f(dt*an0), h0, dtu*bv.x);
        h1 = fmaf(ex2f(dt*an1), h1, dtu*bv.y);
        h2 = fmaf(ex2f(dt*an2), h2, dtu*bv.z);
        h3 = fmaf(ex2f(dt*an3), h3, dtu*bv.w);
        float p = h0*cv.x;
        p = fmaf(h1, cv.y, p);
        p = fmaf(h2, cv.z, p);
        p = fmaf(h3, cv.w, p);
        p += __shfl_xor_sync(0xffffffffu, p, 1, 4);
        p += __shfl_xor_sync(0xffffffffu, p, 2, 4);
        if (nq == 0) su[dl][t] = p + u*ds;   // overwrite u slot (already consumed)
    }
    __syncthreads();

    // coalesced scattered-tile store: 64 d columns x 64 positions
    float* ybase = g_ys + ((long)(k*BD + b)*LL)*DE + dg*64;
    #pragma unroll
    for (int q=tid; q<CT*64; q+=256){
        int t = q>>6, j = q&63;
        int tloc = tloc0 + t;
        int lv = rev ? (LL-1 - tloc) : tloc;
        int lg = vert ? (((lv&63)<<6) | (lv>>6)) : lv;
        ybase[(long)lg*DE + j] = su[j][t];
    }
}

// ---------------- K5: combine 4 dirs + LayerNorm + z-gate ----------------
__global__ void k5_ln(const float* __restrict__ scale, const float* __restrict__ bias)
{
    const int pos = blockIdx.x;
    const int b = pos >> 12;
    const int l = pos & 4095;
    const int d = threadIdx.x;

    float v = 0.f;
    #pragma unroll
    for (int k=0; k<KD; ++k)
        v += g_ys[((long)(k*BD + b)*LL + l)*DE + d];

    float s = v, sq = v*v;
    #pragma unroll
    for (int off=16; off>0; off>>=1){
        s  += __shfl_xor_sync(0xffffffffu, s,  off);
        sq += __shfl_xor_sync(0xffffffffu, sq, off);
    }
    __shared__ float ss[6], sqq[6];
    if ((threadIdx.x & 31) == 0){ ss[threadIdx.x>>5] = s; sqq[threadIdx.x>>5] = sq; }
    __syncthreads();
    float tot=0.f, totq=0.f;
    #pragma unroll
    for (int w=0; w<6; ++w){ tot += ss[w]; totq += sqq[w]; }
    float mu  = tot * (1.0f/DE);
    float var = totq * (1.0f/DE) - mu*mu;
    float rstd = rsqrtf(var + 1e-5f);
    float yn = (v - mu)*rstd*scale[d] + bias[d];
    g_yn[(long)pos*DE + d] = yn * g_z[(long)pos*DE + d];
}

// ---------------- K6: out = yn @ out_proj_w^T ---------------------------
__global__ void k6_outproj(const float* __restrict__ w, float* __restrict__ out)
{
    __shared__ float As[32][65];
    __shared__ float Bs[32][97];
    const int m0 = blockIdx.x*64;
    const int tid = threadIdx.x;
    const int ty = tid>>4, tx = tid&15;
    float acc[4][6] = {};

    for (int k0=0;k0<DE;k0+=32){
        #pragma unroll
        for (int it=0; it<8; ++it){
            int q = tid + it*256;
            int mm = q>>5, kk = q&31;
            As[kk][mm] = g_yn[(long)(m0+mm)*DE + k0+kk];
        }
        #pragma unroll
        for (int it=0; it<12; ++it){
            int q = tid + it*256;
            int nn = q>>5, kk = q&31;
            Bs[kk][nn] = w[nn*DE + k0+kk];
        }
        __syncthreads();
        #pragma unroll
        for (int kk=0; kk<32; ++kk){
            float a[4], bb[6];
            #pragma unroll
            for (int i=0;i<4;i++) a[i] = As[kk][ty*4+i];
            #pragma unroll
            for (int j=0;j<6;j++) bb[j] = Bs[kk][tx*6+j];
            #pragma unroll
            for (int i=0;i<4;i++)
                #pragma unroll
                for (int j=0;j<6;j++) acc[i][j] = fmaf(a[i], bb[j], acc[i][j]);
        }
        __syncthreads();
    }
    #pragma unroll
    for (int i=0;i<4;i++){
        int rowi = m0 + ty*4 + i;
        #pragma unroll
        for (int j=0;j<6;j++)
            out[(long)rowi*DM + tx*6 + j] = acc[i][j];
    }
}

// ---------------- launch -------------------------------------------------
extern "C" void kernel_launch(void* const* d_in, const int* in_sizes, int n_in,
                              void* d_out, int out_size)
{
    const float* x    = (const float*)d_in[0];
    const float* ipw  = (const float*)d_in[1];
    const float* cw   = (const float*)d_in[2];
    const float* cb   = (const float*)d_in[3];
    const float* xpw  = (const float*)d_in[4];
    const float* dtw  = (const float*)d_in[5];
    const float* dtb  = (const float*)d_in[6];
    const float* alog = (const float*)d_in[7];
    const float* dsv  = (const float*)d_in[8];
    const float* lnsc = (const float*)d_in[9];
    const float* lnbi = (const float*)d_in[10];
    const float* opw  = (const float*)d_in[11];
    float* out = (float*)d_out;

    k1_inproj<<<dim3(6,128), 256>>>(x, ipw);
    k2_conv  <<<BD*DE, 256>>>(cw, cb);
    k3_proj  <<<BD*KD*(LL/32), 256>>>(xpw, dtw, dtb);
    k4a_chunk<<<BD*KD*3*CH, 256>>>(alog);
    k4m_combine<<<BD*KD*DE*NS/256, 256>>>();
    k4c_emit <<<BD*KD*3*CH, 256>>>(alog, dsv);
    k5_ln    <<<BD*LL, DE>>>(lnsc, lnbi);
    k6_outproj<<<128, 256>>>(opw, out);
}